// round 12
// baseline (speedup 1.0000x reference)
#include <cuda_runtime.h>
#include <cuda_fp16.h>

// FastPooling "social", pooled formulation:
//  K1 (grid n, 128thr): winner scatter (shared atomicMax, last-write-wins ==
//      max-j; out-of-range peds write zeros to cell 0 -> in_range bit
//      suppresses), per-(warp,cy) compaction, register gather of hidden rows
//      -> g_pool[i][cc*128+h] (fp16).  pooled[i] @ W == sum_winners H rows.
//  K2 (grid 8 x 16): out-partial[cc] = pool[:, cc-slice] @ W[h*16+cc, :] via
//      fp16 HMMA m16n8k16 (proven R7 block shape), fp32 partials.
//  K3: out[i] = relu(bias + sum_cc part[cc][i]).

#define N_MAX   512
#define HID     128
#define GRID_S  32
#define NCELLS  (GRID_S * GRID_S)   // 1024
#define CC_N    16
#define OUTD    128
#define KTOT    (CC_N * HID)        // 2048
#define BM      64
#define SA_LD   136                  // padded half ld (272B)

__device__ __half g_pool[N_MAX * KTOT];              // 2 MB fp16 pooled
__device__ float  g_part[CC_N * N_MAX * OUTD];       // 4 MB fp32 partials

__device__ __forceinline__ unsigned su32(const void* p) {
    return (unsigned)__cvta_generic_to_shared(p);
}
__device__ __forceinline__ void ldsm_x4(unsigned r[4], unsigned addr) {
    asm volatile("ldmatrix.sync.aligned.m8n8.x4.shared.b16 {%0,%1,%2,%3}, [%4];"
                 : "=r"(r[0]), "=r"(r[1]), "=r"(r[2]), "=r"(r[3]) : "r"(addr));
}
__device__ __forceinline__ void ldsm_x4_t(unsigned r[4], unsigned addr) {
    asm volatile("ldmatrix.sync.aligned.m8n8.x4.trans.shared.b16 {%0,%1,%2,%3}, [%4];"
                 : "=r"(r[0]), "=r"(r[1]), "=r"(r[2]), "=r"(r[3]) : "r"(addr));
}
__device__ __forceinline__ void mma16816(float d[4], const unsigned a[4],
                                         const unsigned b0, const unsigned b1) {
    asm volatile("mma.sync.aligned.m16n8k16.row.col.f32.f16.f16.f32 "
                 "{%0,%1,%2,%3}, {%4,%5,%6,%7}, {%8,%9}, {%0,%1,%2,%3};"
                 : "+f"(d[0]), "+f"(d[1]), "+f"(d[2]), "+f"(d[3])
                 : "r"(a[0]), "r"(a[1]), "r"(a[2]), "r"(a[3]), "r"(b0), "r"(b1));
}
__device__ __forceinline__ unsigned cvt2h(float a, float b) {
    __half2 h = __floats2half2_rn(a, b);
    return *reinterpret_cast<unsigned*>(&h);
}

// ---------------------------------------------------------------------------
// K1: scatter + compact + pooled gather of hidden rows. Warp w owns coarse
// x-row cx=w (fine cells [w*256,(w+1)*256)); sub-lists per cy (cc = w*4+cy).
// ---------------------------------------------------------------------------
__global__ __launch_bounds__(128) void pool_kernel(
    const float* __restrict__ hidden,
    const float* __restrict__ obs2,
    int n)
{
    __shared__ int win[NCELLS];        // 4 KB
    __shared__ int lst[CC_N * 64];     // 4 KB: per-(w,cy) segments of 64
    __shared__ int cnt4[CC_N];

    const int i    = blockIdx.x;
    const int t    = threadIdx.x;
    const int w    = t >> 5;
    const int lane = t & 31;

    if (t < CC_N) cnt4[t] = 0;
    #pragma unroll
    for (int s = 0; s < 8; ++s) win[t + 128 * s] = -1;

    const float2* obs = reinterpret_cast<const float2*>(obs2);
    const float xi = obs[i].x;
    const float yi = obs[i].y;

    float2 o[4];
    #pragma unroll
    for (int s = 0; s < 4; ++s) {
        const int j = t + 128 * s;
        o[s] = (j < n) ? obs[j] : make_float2(1e9f, 1e9f);
    }
    __syncthreads();

    #pragma unroll
    for (int s = 0; s < 4; ++s) {
        const int j = t + 128 * s;
        const bool act = (j < n) & (j != i);
        const float ox = (o[s].x - xi) * 4.0f + 16.0f;
        const float oy = (o[s].y - yi) * 4.0f + 16.0f;
        const bool inr = (ox >= 0.f) & (ox < 32.f) & (oy >= 0.f) & (oy < 32.f);
        const int cell = inr ? (((int)ox) * GRID_S + (int)oy) : 0;
        if (act) atomicMax(&win[cell], (j << 1) | (inr ? 1 : 0));
    }
    __syncthreads();

    // compact warp's 256-cell region into 4 per-cy lists (cy = lane>>3)
    const int cy = lane >> 3;
    #pragma unroll
    for (int s = 0; s < 8; ++s) {
        const int c   = w * 256 + s * 32 + lane;      // x = w*8+s, y = lane
        const int enc = win[c];
        const bool valid = (enc >= 0) && (enc & 1);
        const unsigned mask  = __ballot_sync(0xffffffffu, valid);
        const unsigned grp   = 0xFFu << (cy * 8);
        const unsigned gmask = mask & grp;
        const int leader = gmask ? (__ffs(gmask) - 1) : 0;
        int base = 0;
        if (valid && lane == leader)
            base = atomicAdd(&cnt4[w * 4 + cy], __popc(gmask));
        base = __shfl_sync(0xffffffffu, base, leader);
        if (valid) {
            const int rank = __popc(gmask & ((1u << lane) - 1u));
            lst[(w * 4 + cy) * 64 + base + rank] = enc >> 1;   // j
        }
    }
    __syncwarp();

    // gather: per cy, sum hidden rows (float4 per lane), MLP 4
    #pragma unroll
    for (int g = 0; g < 4; ++g) {
        const int seg = (w * 4 + g) * 64;
        const int m   = cnt4[w * 4 + g];
        float4 acc = make_float4(0.f, 0.f, 0.f, 0.f);
        int e = 0;
        for (; e + 3 < m; e += 4) {
            const int j0 = lst[seg + e];     const int j1 = lst[seg + e + 1];
            const int j2 = lst[seg + e + 2]; const int j3 = lst[seg + e + 3];
            const float4 v0 = *reinterpret_cast<const float4*>(hidden + (size_t)j0 * HID + lane * 4);
            const float4 v1 = *reinterpret_cast<const float4*>(hidden + (size_t)j1 * HID + lane * 4);
            const float4 v2 = *reinterpret_cast<const float4*>(hidden + (size_t)j2 * HID + lane * 4);
            const float4 v3 = *reinterpret_cast<const float4*>(hidden + (size_t)j3 * HID + lane * 4);
            acc.x += v0.x + v1.x + v2.x + v3.x;
            acc.y += v0.y + v1.y + v2.y + v3.y;
            acc.z += v0.z + v1.z + v2.z + v3.z;
            acc.w += v0.w + v1.w + v2.w + v3.w;
        }
        for (; e < m; ++e) {
            const int j = lst[seg + e];
            const float4 v = *reinterpret_cast<const float4*>(hidden + (size_t)j * HID + lane * 4);
            acc.x += v.x; acc.y += v.y; acc.z += v.z; acc.w += v.w;
        }
        uint2 u; u.x = cvt2h(acc.x, acc.y); u.y = cvt2h(acc.z, acc.w);
        // pooled k-index = cc*128 + h, cc = w*4+g
        *reinterpret_cast<uint2*>(g_pool + (size_t)i * KTOT + (w * 4 + g) * HID + lane * 4) = u;
    }
}

// ---------------------------------------------------------------------------
// K2: grid (8, 16): j-tile x cc-slice. A = g_pool[j][cc*128..] fp16,
// B = W rows h*16+cc (fp32 -> fp16 at staging). fp32 partial out.
// ---------------------------------------------------------------------------
__global__ __launch_bounds__(256) void gemm_pool_kernel(
    const float* __restrict__ W,
    int n)
{
    __shared__ __align__(16) __half sA[BM][SA_LD];    // 17 KB
    __shared__ __align__(16) __half sB[HID][SA_LD];   // 34 KB

    const int cc    = blockIdx.y;
    const int jbase = blockIdx.x * BM;
    const int t     = threadIdx.x;

    // stage A: 64 rows x 16 uint4 (128 fp16), 4/thread
    #pragma unroll
    for (int s = 0; s < 4; ++s) {
        const int idx  = t + 256 * s;
        const int row  = idx >> 4;
        const int cseg = (idx & 15) * 8;
        uint4 u = make_uint4(0u, 0u, 0u, 0u);
        if (jbase + row < n)
            u = *reinterpret_cast<const uint4*>(
                g_pool + (size_t)(jbase + row) * KTOT + cc * HID + cseg);
        *reinterpret_cast<uint4*>(&sA[row][cseg]) = u;
    }
    // stage B: 128 h-rows x 128 cols, W row h*16+cc (contig 512B), cvt->fp16
    // 2048 uint4 targets, 8/thread; each = 2 LDG.128 + cvt
    #pragma unroll
    for (int s = 0; s < 8; ++s) {
        const int idx  = t + 256 * s;
        const int h    = idx >> 4;
        const int cseg = (idx & 15) * 8;
        const float4* src = reinterpret_cast<const float4*>(
            W + ((size_t)(h * CC_N + cc)) * OUTD + cseg);
        const float4 fa = src[0];
        const float4 fb = src[1];
        uint4 u;
        u.x = cvt2h(fa.x, fa.y); u.y = cvt2h(fa.z, fa.w);
        u.z = cvt2h(fb.x, fb.y); u.w = cvt2h(fb.z, fb.w);
        *reinterpret_cast<uint4*>(&sB[h][cseg]) = u;
    }
    __syncthreads();

    const int wid  = t >> 5;
    const int lane = t & 31;
    const int wc   = wid * 16;
    const int arow = lane & 15;
    const int aseg = (lane >> 4) * 8;

    float d[4][2][4];
    #pragma unroll
    for (int mt = 0; mt < 4; ++mt)
        #pragma unroll
        for (int nt = 0; nt < 2; ++nt)
            #pragma unroll
            for (int q = 0; q < 4; ++q) d[mt][nt][q] = 0.f;

    const unsigned aBase = su32(&sA[0][0]);
    const unsigned bBase = su32(&sB[0][0]);

    #pragma unroll
    for (int ks = 0; ks < 8; ++ks) {
        unsigned bfr[4];
        ldsm_x4_t(bfr, bBase + ((ks * 16 + arow) * SA_LD + wc + aseg) * 2);
        #pragma unroll
        for (int mt = 0; mt < 4; ++mt) {
            unsigned a[4];
            ldsm_x4(a, aBase + ((mt * 16 + arow) * SA_LD + ks * 16 + aseg) * 2);
            mma16816(d[mt][0], a, bfr[0], bfr[1]);
            mma16816(d[mt][1], a, bfr[2], bfr[3]);
        }
    }

    // epilogue: fp32 partials. frag rows lane>>2 (+8), cols (lane&3)*2 (+1)
    #pragma unroll
    for (int mt = 0; mt < 4; ++mt) {
        #pragma unroll
        for (int nt = 0; nt < 2; ++nt) {
            const int jg  = jbase + mt * 16 + (lane >> 2);
            const int col = wc + nt * 8 + (lane & 3) * 2;
            float* basep = g_part + ((size_t)cc * N_MAX) * OUTD;
            if (jg < n)
                *reinterpret_cast<float2*>(basep + (size_t)jg * OUTD + col) =
                    make_float2(d[mt][nt][0], d[mt][nt][1]);
            if (jg + 8 < n)
                *reinterpret_cast<float2*>(basep + (size_t)(jg + 8) * OUTD + col) =
                    make_float2(d[mt][nt][2], d[mt][nt][3]);
        }
    }
}

// ---------------------------------------------------------------------------
// K3: out[i] = relu(bias + sum_cc part[cc][i]).  16 independent LDGs (MLP 16).
// ---------------------------------------------------------------------------
__global__ __launch_bounds__(128) void combine_kernel(
    const float* __restrict__ bias,
    float* __restrict__ out)
{
    const int i = blockIdx.x;
    const int t = threadIdx.x;
    const float* p = g_part + (size_t)i * OUTD + t;
    float s = bias[t];
    #pragma unroll
    for (int cc = 0; cc < CC_N; ++cc)
        s += p[(size_t)cc * N_MAX * OUTD];
    out[(size_t)i * OUTD + t] = fmaxf(s, 0.f);
}

// ---------------------------------------------------------------------------
// inputs: hidden_state (n,128) f32 | obs1 (n,2) (unused) | obs2 (n,2) f32 |
//         W (2048,128) f32 | b (128,) f32   -> out (n,128) f32
// ---------------------------------------------------------------------------
extern "C" void kernel_launch(void* const* d_in, const int* in_sizes, int n_in,
                              void* d_out, int out_size)
{
    const float* hidden = (const float*)d_in[0];
    const float* obs2   = (const float*)d_in[2];
    const float* W      = (const float*)d_in[3];
    const float* bias   = (const float*)d_in[4];
    float*       out    = (float*)d_out;

    const int n = in_sizes[2] / 2;   // 512

    pool_kernel<<<n, 128>>>(hidden, obs2, n);
    dim3 g2((n + BM - 1) / BM, CC_N);
    gemm_pool_kernel<<<g2, 256>>>(W, n);
    combine_kernel<<<n, 128>>>(bias, out);
}

// round 13
// speedup vs baseline: 1.1213x; 1.1213x over previous
#include <cuda_runtime.h>
#include <cuda_fp16.h>

// FastPooling "social", 4-launch, all stages short + wide:
//  K1 scatter (n x 256t): winner grid (shared atomicMax, last-write-wins ==
//     max-j; out-of-range peds hit cell 0 with in_range bit 0 -> suppressed),
//     compact into per-quarter gmem lists g_lst/g_qcnt.
//  K2 gemm (8 x 16): H[j][cc][:] = hidden[j] @ W[:,cc,:], fp16 HMMA m16n8k16,
//     fp32->fp16 conversion fused into staging -> g_Hh.
//  K3 gather (n x 4 x 128t): quarter-list gather of H rows -> g_part[i][q].
//  K4 combine: out[i] = relu(bias + sum_q part[i][q]).

#define N_MAX   512
#define HID     128
#define GRID_S  32
#define NCELLS  (GRID_S * GRID_S)   // 1024
#define QCELLS  256
#define CC_N    16
#define OUTD    128
#define BM      64
#define SA_LD   136                  // padded half ld (272B)

__device__ __half g_Hh[N_MAX * CC_N * OUTD];     // 2 MB fp16 H table
__device__ int    g_lst[N_MAX * NCELLS];         // quarter-segmented lists
__device__ int    g_qcnt[N_MAX * 4];
__device__ float  g_part[N_MAX * 4 * OUTD];      // 1 MB partials

__device__ __forceinline__ unsigned su32(const void* p) {
    return (unsigned)__cvta_generic_to_shared(p);
}
__device__ __forceinline__ void ldsm_x4(unsigned r[4], unsigned addr) {
    asm volatile("ldmatrix.sync.aligned.m8n8.x4.shared.b16 {%0,%1,%2,%3}, [%4];"
                 : "=r"(r[0]), "=r"(r[1]), "=r"(r[2]), "=r"(r[3]) : "r"(addr));
}
__device__ __forceinline__ void ldsm_x4_t(unsigned r[4], unsigned addr) {
    asm volatile("ldmatrix.sync.aligned.m8n8.x4.trans.shared.b16 {%0,%1,%2,%3}, [%4];"
                 : "=r"(r[0]), "=r"(r[1]), "=r"(r[2]), "=r"(r[3]) : "r"(addr));
}
__device__ __forceinline__ void mma16816(float d[4], const unsigned a[4],
                                         const unsigned b0, const unsigned b1) {
    asm volatile("mma.sync.aligned.m16n8k16.row.col.f32.f16.f16.f32 "
                 "{%0,%1,%2,%3}, {%4,%5,%6,%7}, {%8,%9}, {%0,%1,%2,%3};"
                 : "+f"(d[0]), "+f"(d[1]), "+f"(d[2]), "+f"(d[3])
                 : "r"(a[0]), "r"(a[1]), "r"(a[2]), "r"(a[3]), "r"(b0), "r"(b1));
}
__device__ __forceinline__ unsigned cvt2h(float a, float b) {
    __half2 h = __floats2half2_rn(a, b);
    return *reinterpret_cast<unsigned*>(&h);
}

// ---------------------------------------------------------------------------
// K1: scatter + quarter compaction. Quarter q = cells [q*256,(q+1)*256).
// ---------------------------------------------------------------------------
__global__ __launch_bounds__(256) void scatter_kernel(
    const float* __restrict__ obs2,
    int n)
{
    __shared__ int win[NCELLS];
    __shared__ int cnt4[4];

    const int i    = blockIdx.x;
    const int t    = threadIdx.x;
    const int lane = t & 31;

    if (t < 4) cnt4[t] = 0;
    #pragma unroll
    for (int s = 0; s < 4; ++s) win[t + 256 * s] = -1;

    const float2* obs = reinterpret_cast<const float2*>(obs2);
    const float xi = obs[i].x;
    const float yi = obs[i].y;

    float2 o[2];
    #pragma unroll
    for (int s = 0; s < 2; ++s) {
        const int j = t + 256 * s;
        o[s] = (j < n) ? obs[j] : make_float2(1e9f, 1e9f);
    }
    __syncthreads();

    #pragma unroll
    for (int s = 0; s < 2; ++s) {
        const int j = t + 256 * s;
        const bool act = (j < n) & (j != i);
        const float ox = (o[s].x - xi) * 4.0f + 16.0f;
        const float oy = (o[s].y - yi) * 4.0f + 16.0f;
        const bool inr = (ox >= 0.f) & (ox < 32.f) & (oy >= 0.f) & (oy < 32.f);
        const int cell = inr ? (((int)ox) * GRID_S + (int)oy) : 0;
        if (act) atomicMax(&win[cell], (j << 1) | (inr ? 1 : 0));
    }
    __syncthreads();

    // quarter s == cell block [s*256, s*256+256); cc = s*4 + ((c>>3)&3)
    #pragma unroll
    for (int s = 0; s < 4; ++s) {
        const int c   = s * 256 + t;
        const int enc = win[c];
        const bool valid = (enc >= 0) && (enc & 1);
        const unsigned mask = __ballot_sync(0xffffffffu, valid);
        if (mask) {
            const int leader = __ffs(mask) - 1;
            int base = 0;
            if (lane == leader) base = atomicAdd(&cnt4[s], __popc(mask));
            base = __shfl_sync(0xffffffffu, base, leader);
            if (valid) {
                const int j  = enc >> 1;
                const int cc = s * 4 + ((c >> 3) & 3);
                g_lst[i * NCELLS + s * QCELLS + base +
                      __popc(mask & ((1u << lane) - 1u))] = j * CC_N + cc;
            }
        }
    }
    __syncthreads();
    if (t < 4) g_qcnt[i * 4 + t] = cnt4[t];
}

// ---------------------------------------------------------------------------
// K2: H-table GEMM. Block = 64 j-rows x 128 cols (one cc). Grid (8, 16).
// fp32 inputs converted to fp16 during staging.
// ---------------------------------------------------------------------------
__global__ __launch_bounds__(256) void gemm_kernel(
    const float* __restrict__ hidden,
    const float* __restrict__ W,
    int n)
{
    __shared__ __align__(16) __half sA[BM][SA_LD];    // 17 KB
    __shared__ __align__(16) __half sB[HID][SA_LD];   // 34 KB

    const int cc    = blockIdx.y;
    const int jbase = blockIdx.x * BM;
    const int t     = threadIdx.x;

    // stage A: 64 x 128 fp32 -> fp16. 2048 float4, 8/thread.
    #pragma unroll
    for (int s = 0; s < 8; ++s) {
        const int idx  = t + 256 * s;
        const int row  = idx >> 5;
        const int col4 = (idx & 31) * 4;
        float4 f = make_float4(0.f, 0.f, 0.f, 0.f);
        if (jbase + row < n)
            f = *reinterpret_cast<const float4*>(hidden + (size_t)(jbase + row) * HID + col4);
        uint2 u; u.x = cvt2h(f.x, f.y); u.y = cvt2h(f.z, f.w);
        *reinterpret_cast<uint2*>(&sA[row][col4]) = u;
    }
    // stage B: 128 k-rows (W row k*16+cc, contiguous 512B) -> fp16.
    #pragma unroll
    for (int s = 0; s < 16; ++s) {
        const int idx  = t + 256 * s;
        const int k    = idx >> 5;
        const int col4 = (idx & 31) * 4;
        const float4 f = *reinterpret_cast<const float4*>(
            W + ((size_t)(k * CC_N + cc)) * OUTD + col4);
        uint2 u; u.x = cvt2h(f.x, f.y); u.y = cvt2h(f.z, f.w);
        *reinterpret_cast<uint2*>(&sB[k][col4]) = u;
    }
    __syncthreads();

    const int wid  = t >> 5;
    const int lane = t & 31;
    const int wc   = wid * 16;
    const int arow = lane & 15;
    const int aseg = (lane >> 4) * 8;

    float d[4][2][4];
    #pragma unroll
    for (int mt = 0; mt < 4; ++mt)
        #pragma unroll
        for (int nt = 0; nt < 2; ++nt)
            #pragma unroll
            for (int q = 0; q < 4; ++q) d[mt][nt][q] = 0.f;

    const unsigned aBase = su32(&sA[0][0]);
    const unsigned bBase = su32(&sB[0][0]);

    #pragma unroll
    for (int ks = 0; ks < 8; ++ks) {
        unsigned bfr[4];
        ldsm_x4_t(bfr, bBase + ((ks * 16 + arow) * SA_LD + wc + aseg) * 2);
        #pragma unroll
        for (int mt = 0; mt < 4; ++mt) {
            unsigned a[4];
            ldsm_x4(a, aBase + ((mt * 16 + arow) * SA_LD + ks * 16 + aseg) * 2);
            mma16816(d[mt][0], a, bfr[0], bfr[1]);
            mma16816(d[mt][1], a, bfr[2], bfr[3]);
        }
    }

    #pragma unroll
    for (int mt = 0; mt < 4; ++mt) {
        #pragma unroll
        for (int nt = 0; nt < 2; ++nt) {
            const int jg  = jbase + mt * 16 + (lane >> 2);
            const int col = wc + nt * 8 + (lane & 3) * 2;
            const unsigned lo = cvt2h(d[mt][nt][0], d[mt][nt][1]);
            const unsigned hi = cvt2h(d[mt][nt][2], d[mt][nt][3]);
            if (jg < n)
                *reinterpret_cast<unsigned*>(g_Hh + ((size_t)jg * CC_N + cc) * OUTD + col) = lo;
            if (jg + 8 < n)
                *reinterpret_cast<unsigned*>(g_Hh + ((size_t)(jg + 8) * CC_N + cc) * OUTD + col) = hi;
        }
    }
}

// ---------------------------------------------------------------------------
// K3: gather. Grid (n, 4), 128 thr. Quarter list from g_lst, MLP-8 gather.
// ---------------------------------------------------------------------------
__global__ __launch_bounds__(128) void gather_kernel(int n)
{
    __shared__ __align__(16) float red[4][OUTD];   // 2 KB
    __shared__ int lst[QCELLS];                    // 1 KB

    const int i    = blockIdx.x;
    const int q    = blockIdx.y;
    const int t    = threadIdx.x;
    const int w    = t >> 5;
    const int lane = t & 31;

    const int m = g_qcnt[i * 4 + q];
    for (int e = t; e < m; e += 128)
        lst[e] = g_lst[i * NCELLS + q * QCELLS + e];
    __syncthreads();

    float4 acc0 = make_float4(0.f, 0.f, 0.f, 0.f);
    float4 acc1 = make_float4(0.f, 0.f, 0.f, 0.f);
    const int co = lane * 4;

    #define ACCUM(A, u) do {                                              \
        const __half2 _h0 = *reinterpret_cast<const __half2*>(&(u).x);    \
        const __half2 _h1 = *reinterpret_cast<const __half2*>(&(u).y);    \
        const float2 _f0 = __half22float2(_h0);                           \
        const float2 _f1 = __half22float2(_h1);                           \
        A.x += _f0.x; A.y += _f0.y; A.z += _f1.x; A.w += _f1.y;           \
    } while (0)

    int e = w;
    for (; e + 28 < m; e += 32) {
        const int p0 = lst[e];      const int p1 = lst[e + 4];
        const int p2 = lst[e + 8];  const int p3 = lst[e + 12];
        const int p4 = lst[e + 16]; const int p5 = lst[e + 20];
        const int p6 = lst[e + 24]; const int p7 = lst[e + 28];
        const uint2 v0 = *reinterpret_cast<const uint2*>(g_Hh + (size_t)p0 * OUTD + co);
        const uint2 v1 = *reinterpret_cast<const uint2*>(g_Hh + (size_t)p1 * OUTD + co);
        const uint2 v2 = *reinterpret_cast<const uint2*>(g_Hh + (size_t)p2 * OUTD + co);
        const uint2 v3 = *reinterpret_cast<const uint2*>(g_Hh + (size_t)p3 * OUTD + co);
        const uint2 v4 = *reinterpret_cast<const uint2*>(g_Hh + (size_t)p4 * OUTD + co);
        const uint2 v5 = *reinterpret_cast<const uint2*>(g_Hh + (size_t)p5 * OUTD + co);
        const uint2 v6 = *reinterpret_cast<const uint2*>(g_Hh + (size_t)p6 * OUTD + co);
        const uint2 v7 = *reinterpret_cast<const uint2*>(g_Hh + (size_t)p7 * OUTD + co);
        ACCUM(acc0, v0); ACCUM(acc1, v1); ACCUM(acc0, v2); ACCUM(acc1, v3);
        ACCUM(acc0, v4); ACCUM(acc1, v5); ACCUM(acc0, v6); ACCUM(acc1, v7);
    }
    for (; e < m; e += 4) {
        const int p = lst[e];
        const uint2 v = *reinterpret_cast<const uint2*>(g_Hh + (size_t)p * OUTD + co);
        ACCUM(acc0, v);
    }
    #undef ACCUM
    acc0.x += acc1.x; acc0.y += acc1.y; acc0.z += acc1.z; acc0.w += acc1.w;

    *reinterpret_cast<float4*>(&red[w][co]) = acc0;
    __syncthreads();

    if (t < OUTD)
        g_part[((size_t)i * 4 + blockIdx.y) * OUTD + t] =
            red[0][t] + red[1][t] + red[2][t] + red[3][t];
}

// ---------------------------------------------------------------------------
// K4: out[i] = relu(bias + sum_q part[i][q]).
// ---------------------------------------------------------------------------
__global__ __launch_bounds__(128) void combine_kernel(
    const float* __restrict__ bias,
    float* __restrict__ out)
{
    const int i = blockIdx.x;
    const int t = threadIdx.x;
    const float* p = g_part + (size_t)i * 4 * OUTD + t;
    const float s = bias[t] + p[0] + p[OUTD] + p[2 * OUTD] + p[3 * OUTD];
    out[(size_t)i * OUTD + t] = fmaxf(s, 0.f);
}

// ---------------------------------------------------------------------------
// inputs: hidden_state (n,128) f32 | obs1 (n,2) (unused) | obs2 (n,2) f32 |
//         W (2048,128) f32 | b (128,) f32   -> out (n,128) f32
// ---------------------------------------------------------------------------
extern "C" void kernel_launch(void* const* d_in, const int* in_sizes, int n_in,
                              void* d_out, int out_size)
{
    const float* hidden = (const float*)d_in[0];
    const float* obs2   = (const float*)d_in[2];
    const float* W      = (const float*)d_in[3];
    const float* bias   = (const float*)d_in[4];
    float*       out    = (float*)d_out;

    const int n = in_sizes[2] / 2;   // 512

    scatter_kernel<<<n, 256>>>(obs2, n);
    dim3 g2((n + BM - 1) / BM, CC_N);
    gemm_kernel<<<g2, 256>>>(hidden, W, n);
    dim3 g3(n, 4);
    gather_kernel<<<g3, 128>>>(n);
    combine_kernel<<<n, 128>>>(bias, out);
}

// round 14
// speedup vs baseline: 1.1670x; 1.0408x over previous
#include <cuda_runtime.h>
#include <cuda_fp16.h>

// FastPooling "social", 2-launch:
//  K1 (combined): blocks [0,128): H[j][cc][:] = hidden[j] @ W[:,cc,:] via fp16
//     HMMA m16n8k16 (fp32->fp16 in staging) -> g_Hh.  blocks [128,128+n):
//     winner scatter (shared atomicMax, last-write-wins == max-j; out-of-range
//     peds hit cell 0 with in_range=0 -> suppressed) + quarter compaction ->
//     g_lst/g_qcnt.  The two phases are independent and overlap on-chip.
//  K2 (fused): per ped, stage 4 quarter lists into smem, 8-warp MLP-8 gather
//     of H rows, smem reduce, bias + relu -> out.

#define N_MAX   512
#define HID     128
#define GRID_S  32
#define NCELLS  (GRID_S * GRID_S)   // 1024
#define QCELLS  256
#define CC_N    16
#define OUTD    128
#define BM      64
#define SA_LD   136                  // padded half ld (272B)
#define GEMM_BLOCKS 128              // 8 j-tiles x 16 cc

__device__ __half g_Hh[N_MAX * CC_N * OUTD];     // 2 MB fp16 H table
__device__ int    g_lst[N_MAX * NCELLS];         // quarter-segmented lists
__device__ int    g_qcnt[N_MAX * 4];

__device__ __forceinline__ unsigned su32(const void* p) {
    return (unsigned)__cvta_generic_to_shared(p);
}
__device__ __forceinline__ void ldsm_x4(unsigned r[4], unsigned addr) {
    asm volatile("ldmatrix.sync.aligned.m8n8.x4.shared.b16 {%0,%1,%2,%3}, [%4];"
                 : "=r"(r[0]), "=r"(r[1]), "=r"(r[2]), "=r"(r[3]) : "r"(addr));
}
__device__ __forceinline__ void ldsm_x4_t(unsigned r[4], unsigned addr) {
    asm volatile("ldmatrix.sync.aligned.m8n8.x4.trans.shared.b16 {%0,%1,%2,%3}, [%4];"
                 : "=r"(r[0]), "=r"(r[1]), "=r"(r[2]), "=r"(r[3]) : "r"(addr));
}
__device__ __forceinline__ void mma16816(float d[4], const unsigned a[4],
                                         const unsigned b0, const unsigned b1) {
    asm volatile("mma.sync.aligned.m16n8k16.row.col.f32.f16.f16.f32 "
                 "{%0,%1,%2,%3}, {%4,%5,%6,%7}, {%8,%9}, {%0,%1,%2,%3};"
                 : "+f"(d[0]), "+f"(d[1]), "+f"(d[2]), "+f"(d[3])
                 : "r"(a[0]), "r"(a[1]), "r"(a[2]), "r"(a[3]), "r"(b0), "r"(b1));
}
__device__ __forceinline__ unsigned cvt2h(float a, float b) {
    __half2 h = __floats2half2_rn(a, b);
    return *reinterpret_cast<unsigned*>(&h);
}

// ---------------------------------------------------------------------------
// K1: combined GEMM (blocks < 128) + scatter (blocks >= 128).
// ---------------------------------------------------------------------------
__global__ __launch_bounds__(256) void gemm_scatter_kernel(
    const float* __restrict__ hidden,
    const float* __restrict__ W,
    const float* __restrict__ obs2,
    int n)
{
    const int b = blockIdx.x;
    const int t = threadIdx.x;

    if (b < GEMM_BLOCKS) {
        // ------------------------- GEMM path -------------------------
        __shared__ __align__(16) __half sA[BM][SA_LD];    // 17 KB
        __shared__ __align__(16) __half sB[HID][SA_LD];   // 34 KB

        const int cc    = b & 15;
        const int jbase = (b >> 4) * BM;

        #pragma unroll
        for (int s = 0; s < 8; ++s) {
            const int idx  = t + 256 * s;
            const int row  = idx >> 5;
            const int col4 = (idx & 31) * 4;
            float4 f = make_float4(0.f, 0.f, 0.f, 0.f);
            if (jbase + row < n)
                f = *reinterpret_cast<const float4*>(hidden + (size_t)(jbase + row) * HID + col4);
            uint2 u; u.x = cvt2h(f.x, f.y); u.y = cvt2h(f.z, f.w);
            *reinterpret_cast<uint2*>(&sA[row][col4]) = u;
        }
        #pragma unroll
        for (int s = 0; s < 16; ++s) {
            const int idx  = t + 256 * s;
            const int k    = idx >> 5;
            const int col4 = (idx & 31) * 4;
            const float4 f = *reinterpret_cast<const float4*>(
                W + ((size_t)(k * CC_N + cc)) * OUTD + col4);
            uint2 u; u.x = cvt2h(f.x, f.y); u.y = cvt2h(f.z, f.w);
            *reinterpret_cast<uint2*>(&sB[k][col4]) = u;
        }
        __syncthreads();

        const int wid  = t >> 5;
        const int lane = t & 31;
        const int wc   = wid * 16;
        const int arow = lane & 15;
        const int aseg = (lane >> 4) * 8;

        float d[4][2][4];
        #pragma unroll
        for (int mt = 0; mt < 4; ++mt)
            #pragma unroll
            for (int nt = 0; nt < 2; ++nt)
                #pragma unroll
                for (int q = 0; q < 4; ++q) d[mt][nt][q] = 0.f;

        const unsigned aBase = su32(&sA[0][0]);
        const unsigned bBase = su32(&sB[0][0]);

        #pragma unroll
        for (int ks = 0; ks < 8; ++ks) {
            unsigned bfr[4];
            ldsm_x4_t(bfr, bBase + ((ks * 16 + arow) * SA_LD + wc + aseg) * 2);
            #pragma unroll
            for (int mt = 0; mt < 4; ++mt) {
                unsigned a[4];
                ldsm_x4(a, aBase + ((mt * 16 + arow) * SA_LD + ks * 16 + aseg) * 2);
                mma16816(d[mt][0], a, bfr[0], bfr[1]);
                mma16816(d[mt][1], a, bfr[2], bfr[3]);
            }
        }

        #pragma unroll
        for (int mt = 0; mt < 4; ++mt) {
            #pragma unroll
            for (int nt = 0; nt < 2; ++nt) {
                const int jg  = jbase + mt * 16 + (lane >> 2);
                const int col = wc + nt * 8 + (lane & 3) * 2;
                const unsigned lo = cvt2h(d[mt][nt][0], d[mt][nt][1]);
                const unsigned hi = cvt2h(d[mt][nt][2], d[mt][nt][3]);
                if (jg < n)
                    *reinterpret_cast<unsigned*>(g_Hh + ((size_t)jg * CC_N + cc) * OUTD + col) = lo;
                if (jg + 8 < n)
                    *reinterpret_cast<unsigned*>(g_Hh + ((size_t)(jg + 8) * CC_N + cc) * OUTD + col) = hi;
            }
        }
        return;
    }

    // ------------------------- scatter path -------------------------
    const int i = b - GEMM_BLOCKS;
    if (i >= n) return;

    __shared__ int win[NCELLS];
    __shared__ int cnt4[4];

    const int lane = t & 31;

    if (t < 4) cnt4[t] = 0;
    #pragma unroll
    for (int s = 0; s < 4; ++s) win[t + 256 * s] = -1;

    const float2* obs = reinterpret_cast<const float2*>(obs2);
    const float xi = obs[i].x;
    const float yi = obs[i].y;

    float2 o[2];
    #pragma unroll
    for (int s = 0; s < 2; ++s) {
        const int j = t + 256 * s;
        o[s] = (j < n) ? obs[j] : make_float2(1e9f, 1e9f);
    }
    __syncthreads();

    #pragma unroll
    for (int s = 0; s < 2; ++s) {
        const int j = t + 256 * s;
        const bool act = (j < n) & (j != i);
        const float ox = (o[s].x - xi) * 4.0f + 16.0f;
        const float oy = (o[s].y - yi) * 4.0f + 16.0f;
        const bool inr = (ox >= 0.f) & (ox < 32.f) & (oy >= 0.f) & (oy < 32.f);
        const int cell = inr ? (((int)ox) * GRID_S + (int)oy) : 0;
        if (act) atomicMax(&win[cell], (j << 1) | (inr ? 1 : 0));
    }
    __syncthreads();

    #pragma unroll
    for (int s = 0; s < 4; ++s) {
        const int c   = s * 256 + t;
        const int enc = win[c];
        const bool valid = (enc >= 0) && (enc & 1);
        const unsigned mask = __ballot_sync(0xffffffffu, valid);
        if (mask) {
            const int leader = __ffs(mask) - 1;
            int base = 0;
            if (lane == leader) base = atomicAdd(&cnt4[s], __popc(mask));
            base = __shfl_sync(0xffffffffu, base, leader);
            if (valid) {
                const int j  = enc >> 1;
                const int cc = s * 4 + ((c >> 3) & 3);
                g_lst[i * NCELLS + s * QCELLS + base +
                      __popc(mask & ((1u << lane) - 1u))] = j * CC_N + cc;
            }
        }
    }
    __syncthreads();
    if (t < 4) g_qcnt[i * 4 + t] = cnt4[t];
}

// ---------------------------------------------------------------------------
// K2: fused gather + combine. Grid n, 256 thr (8 warps). Lists merged in smem,
// 8 warps stride the merged list (MLP 8), reduce, bias + relu -> out.
// ---------------------------------------------------------------------------
__global__ __launch_bounds__(256) void gather_out_kernel(
    const float* __restrict__ bias,
    float* __restrict__ out,
    int n)
{
    __shared__ __align__(16) float red[8][OUTD];   // 4 KB
    __shared__ int lst[NCELLS];                    // 4 KB
    __shared__ int offs[5];

    const int i    = blockIdx.x;
    const int t    = threadIdx.x;
    const int w    = t >> 5;
    const int lane = t & 31;

    if (t == 0) {
        int acc = 0;
        #pragma unroll
        for (int q = 0; q < 4; ++q) {
            offs[q] = acc;
            acc += g_qcnt[i * 4 + q];
        }
        offs[4] = acc;
    }
    __syncthreads();

    // stage 4 quarter lists contiguously
    #pragma unroll
    for (int q = 0; q < 4; ++q) {
        const int cnt = offs[q + 1] - offs[q];
        for (int e = t; e < cnt; e += 256)
            lst[offs[q] + e] = g_lst[i * NCELLS + q * QCELLS + e];
    }
    __syncthreads();
    const int m = offs[4];

    float4 acc0 = make_float4(0.f, 0.f, 0.f, 0.f);
    float4 acc1 = make_float4(0.f, 0.f, 0.f, 0.f);
    const int co = lane * 4;

    #define ACCUM(A, u) do {                                              \
        const __half2 _h0 = *reinterpret_cast<const __half2*>(&(u).x);    \
        const __half2 _h1 = *reinterpret_cast<const __half2*>(&(u).y);    \
        const float2 _f0 = __half22float2(_h0);                           \
        const float2 _f1 = __half22float2(_h1);                           \
        A.x += _f0.x; A.y += _f0.y; A.z += _f1.x; A.w += _f1.y;           \
    } while (0)

    int e = w;
    for (; e + 56 < m; e += 64) {           // 8 uint2 LDGs in flight
        const int p0 = lst[e];      const int p1 = lst[e + 8];
        const int p2 = lst[e + 16]; const int p3 = lst[e + 24];
        const int p4 = lst[e + 32]; const int p5 = lst[e + 40];
        const int p6 = lst[e + 48]; const int p7 = lst[e + 56];
        const uint2 v0 = *reinterpret_cast<const uint2*>(g_Hh + (size_t)p0 * OUTD + co);
        const uint2 v1 = *reinterpret_cast<const uint2*>(g_Hh + (size_t)p1 * OUTD + co);
        const uint2 v2 = *reinterpret_cast<const uint2*>(g_Hh + (size_t)p2 * OUTD + co);
        const uint2 v3 = *reinterpret_cast<const uint2*>(g_Hh + (size_t)p3 * OUTD + co);
        const uint2 v4 = *reinterpret_cast<const uint2*>(g_Hh + (size_t)p4 * OUTD + co);
        const uint2 v5 = *reinterpret_cast<const uint2*>(g_Hh + (size_t)p5 * OUTD + co);
        const uint2 v6 = *reinterpret_cast<const uint2*>(g_Hh + (size_t)p6 * OUTD + co);
        const uint2 v7 = *reinterpret_cast<const uint2*>(g_Hh + (size_t)p7 * OUTD + co);
        ACCUM(acc0, v0); ACCUM(acc1, v1); ACCUM(acc0, v2); ACCUM(acc1, v3);
        ACCUM(acc0, v4); ACCUM(acc1, v5); ACCUM(acc0, v6); ACCUM(acc1, v7);
    }
    for (; e < m; e += 8) {
        const int p = lst[e];
        const uint2 v = *reinterpret_cast<const uint2*>(g_Hh + (size_t)p * OUTD + co);
        ACCUM(acc0, v);
    }
    #undef ACCUM
    acc0.x += acc1.x; acc0.y += acc1.y; acc0.z += acc1.z; acc0.w += acc1.w;

    *reinterpret_cast<float4*>(&red[w][co]) = acc0;
    __syncthreads();

    if (t < OUTD) {
        float s = bias[t];
        #pragma unroll
        for (int r = 0; r < 8; ++r) s += red[r][t];
        out[(size_t)i * OUTD + t] = fmaxf(s, 0.f);
    }
}

// ---------------------------------------------------------------------------
// inputs: hidden_state (n,128) f32 | obs1 (n,2) (unused) | obs2 (n,2) f32 |
//         W (2048,128) f32 | b (128,) f32   -> out (n,128) f32
// ---------------------------------------------------------------------------
extern "C" void kernel_launch(void* const* d_in, const int* in_sizes, int n_in,
                              void* d_out, int out_size)
{
    const float* hidden = (const float*)d_in[0];
    const float* obs2   = (const float*)d_in[2];
    const float* W      = (const float*)d_in[3];
    const float* bias   = (const float*)d_in[4];
    float*       out    = (float*)d_out;

    const int n = in_sizes[2] / 2;   // 512

    gemm_scatter_kernel<<<GEMM_BLOCKS + n, 256>>>(hidden, W, obs2, n);
    gather_out_kernel<<<n, 256>>>(bias, out, n);
}